// round 8
// baseline (speedup 1.0000x reference)
#include <cuda_runtime.h>

// Problem constants (fixed by setup_inputs)
constexpr int B = 4, H = 1024, W = 1024;
constexpr int TX = 32;          // output tile width
constexpr int TY = 16;          // output tile height (2 rows per thread)
constexpr int HX = TX + 10;     // 42: halo tile width
constexpr int HY = TY + 10;     // 26: halo tile height

__device__ __forceinline__ float rcpa(float x) {
    float r; asm("rcp.approx.f32 %0,%1;" : "=f"(r) : "f"(x)); return r;
}

#define MK 1e30f
// C1G[k][c]: k=0 and k=12 are OOB pads (weight 0 via 1e30).
// k=1..11 hold (dist - 0.5) for dy offsets -5..5; disk-mask zeros replaced by
// 1e30 so __saturatef(coc - c1) == 0 there.
__device__ const float C1G[13][11] = {
  {MK,MK,MK,MK,MK,MK,MK,MK,MK,MK,MK},
  {MK,MK,MK,4.885164807f,4.599019514f,4.5f,4.599019514f,4.885164807f,MK,MK,MK},
  {MK,MK,4.5f,3.972135955f,3.623105626f,3.5f,3.623105626f,3.972135955f,4.5f,MK,MK},
  {MK,4.5f,3.742640687f,3.105551276f,2.662277660f,2.5f,2.662277660f,3.105551276f,3.742640687f,4.5f,MK},
  {4.885164807f,3.972135955f,3.105551276f,2.328427125f,1.736067977f,1.5f,1.736067977f,2.328427125f,3.105551276f,3.972135955f,4.885164807f},
  {4.599019514f,3.623105626f,2.662277660f,1.736067977f,0.914213562f,0.5f,0.914213562f,1.736067977f,2.662277660f,3.623105626f,4.599019514f},
  {4.5f,3.5f,2.5f,1.5f,0.5f,-0.5f,0.5f,1.5f,2.5f,3.5f,4.5f},
  {4.599019514f,3.623105626f,2.662277660f,1.736067977f,0.914213562f,0.5f,0.914213562f,1.736067977f,2.662277660f,3.623105626f,4.599019514f},
  {4.885164807f,3.972135955f,3.105551276f,2.328427125f,1.736067977f,1.5f,1.736067977f,2.328427125f,3.105551276f,3.972135955f,4.885164807f},
  {MK,4.5f,3.742640687f,3.105551276f,2.662277660f,2.5f,2.662277660f,3.105551276f,3.742640687f,4.5f,MK},
  {MK,MK,4.5f,3.972135955f,3.623105626f,3.5f,3.623105626f,3.972135955f,4.5f,MK,MK},
  {MK,MK,MK,4.885164807f,4.599019514f,4.5f,4.599019514f,4.885164807f,MK,MK,MK},
  {MK,MK,MK,MK,MK,MK,MK,MK,MK,MK,MK}
};

__global__ __launch_bounds__(256, 8)
void scatter_render_kernel(const float* __restrict__ x,
                           const float* __restrict__ lens,
                           float* __restrict__ out)
{
    __shared__ __align__(16) float4 s4[HY][HX];   // (r, g, b, inv_es = e^{-4 disp})
    __shared__ float            sco[HY][HX];      // coc
    __shared__ __align__(8) float2 sP[12][11];    // (c1_out0, c1_out1) per (sr, c)

    const int b   = blockIdx.z;
    const int gx0 = blockIdx.x * TX;
    const int gy0 = blockIdx.y * TY;

    const float scale = fabsf(lens[b]);
    const float* __restrict__ xb = x + (size_t)b * 4 * H * W;
    const float* __restrict__ pr = xb;
    const float* __restrict__ pg = xb + H * W;
    const float* __restrict__ pb = xb + 2 * H * W;
    const float* __restrict__ pd = xb + 3 * H * W;

    // ---- cooperative halo-tile fill (with edge clamp) ----
    const int tid = threadIdx.y * TX + threadIdx.x;
    for (int idx = tid; idx < HY * HX; idx += 256) {
        int yy = idx / HX;
        int xx = idx - yy * HX;
        int sy = gy0 + yy - 5; sy = min(max(sy, 0), H - 1);
        int sx = gx0 + xx - 5; sx = min(max(sx, 0), W - 1);
        int o  = sy * W + sx;
        float d  = pd[o];
        s4[yy][xx]  = make_float4(pr[o], pg[o], pb[o], __expf(-4.0f * d));
        sco[yy][xx] = scale * fabsf(d);
    }
    // ---- constants pair table: sP[sr][c] = (C1G[sr+1][c], C1G[sr][c]) ----
    if (tid < 132) {
        int sr = tid / 11, c = tid - sr * 11;
        sP[sr][c] = make_float2(C1G[sr + 1][c], C1G[sr][c]);
    }
    __syncthreads();

    // ---- main gather: each thread owns 2 vertically adjacent outputs ----
    const int tx = threadIdx.x;
    const int ry = 2 * threadIdx.y;

    // ed = e^{+4 disp_dst} = rcp(inv_es at dst)
    const float ed0 = rcpa(s4[ry + 5][tx + 5].w);
    const float ed1 = rcpa(s4[ry + 6][tx + 5].w);

    float nr0 = 0.f, ng0 = 0.f, nb0 = 0.f, nd0 = 0.f;
    float nr1 = 0.f, ng1 = 0.f, nb1 = 0.f, nd1 = 0.f;

    const float4* p4 = &s4[ry][tx];
    const float*  pc = &sco[ry][tx];
    const float2* pp = &sP[0][0];

    #pragma unroll 1
    for (int sr = 0; sr < 12; ++sr) {       // union of both outputs' 11 rows
        #pragma unroll
        for (int c = 0; c < 11; ++c) {
            const float4 f4 = p4[c];        // r, g, b, inv_es
            const float  cc = pc[c];        // coc
            const float2 c1 = pp[c];        // (c1 for out0, c1 for out1)
            const float w0  = __saturatef(cc - c1.x);
            const float w1  = __saturatef(cc - c1.y);
            const float oc0 = rcpa(fmaf(ed0, f4.w, 1.0f));   // sigmoid gate
            const float oc1 = rcpa(fmaf(ed1, f4.w, 1.0f));
            const float wo0 = w0 * oc0;
            const float wo1 = w1 * oc1;
            nr0 = fmaf(wo0, f4.x, nr0);
            ng0 = fmaf(wo0, f4.y, ng0);
            nb0 = fmaf(wo0, f4.z, nb0);
            nd0 += wo0;
            nr1 = fmaf(wo1, f4.x, nr1);
            ng1 = fmaf(wo1, f4.y, ng1);
            nb1 = fmaf(wo1, f4.z, nb1);
            nd1 += wo1;
        }
        p4 += HX; pc += HX; pp += 11;
    }

    // ---- epilogue: normalize and store 2 outputs x 3 channels ----
    const float i0 = rcpa(nd0 + 1e-8f);
    const float i1 = rcpa(nd1 + 1e-8f);

    const int gx = gx0 + tx;
    const int gy = gy0 + ry;
    float* __restrict__ ob = out + (size_t)b * 3 * H * W;
    const int o0 = gy * W + gx;
    const int o1 = o0 + W;
    ob[o0]             = nr0 * i0;
    ob[H * W + o0]     = ng0 * i0;
    ob[2 * H * W + o0] = nb0 * i0;
    ob[o1]             = nr1 * i1;
    ob[H * W + o1]     = ng1 * i1;
    ob[2 * H * W + o1] = nb1 * i1;
}

extern "C" void kernel_launch(void* const* d_in, const int* in_sizes, int n_in,
                              void* d_out, int out_size)
{
    const float* x    = (const float*)d_in[0];
    const float* lens = (const float*)d_in[1];
    float* out        = (float*)d_out;

    dim3 block(TX, TY / 2, 1);              // 32 x 8 = 256 threads
    dim3 grid(W / TX, H / TY, B);           // 32 x 64 x 4
    scatter_render_kernel<<<grid, block>>>(x, lens, out);
}

// round 10
// speedup vs baseline: 1.5286x; 1.5286x over previous
#include <cuda_runtime.h>

// Problem constants (fixed by setup_inputs)
constexpr int B = 4, H = 1024, W = 1024;
constexpr int TX = 32;          // output tile width
constexpr int TY = 16;          // output tile height (2 rows per thread)
constexpr int HX = TX + 10;     // 42: halo tile width
constexpr int HY = TY + 10;     // 26: halo tile height

// Disk rows (dy = -5..5): column start and width of the in-mask span, in
// kernel-column coords c = dx+5 (0..10). Row widths 5,7,9,11,11,11,11,11,9,7,5.
__device__ constexpr int ST[11] = {3, 2, 1, 0, 0, 0, 0, 0, 1, 2, 3};
__device__ constexpr int WD[11] = {5, 7, 9, 11, 11, 11, 11, 11, 9, 7, 5};

#define MK 1e30f
// QD[dy+5][dx+5] = dist - 0.5 (entries outside the disk are never evaluated;
// MK kept only as a safe filler).
__device__ constexpr float QD[11][11] = {
  {MK,MK,MK,4.885164807f,4.599019514f,4.5f,4.599019514f,4.885164807f,MK,MK,MK},
  {MK,MK,4.5f,3.972135955f,3.623105626f,3.5f,3.623105626f,3.972135955f,4.5f,MK,MK},
  {MK,4.5f,3.742640687f,3.105551276f,2.662277660f,2.5f,2.662277660f,3.105551276f,3.742640687f,4.5f,MK},
  {4.885164807f,3.972135955f,3.105551276f,2.328427125f,1.736067977f,1.5f,1.736067977f,2.328427125f,3.105551276f,3.972135955f,4.885164807f},
  {4.599019514f,3.623105626f,2.662277660f,1.736067977f,0.914213562f,0.5f,0.914213562f,1.736067977f,2.662277660f,3.623105626f,4.599019514f},
  {4.5f,3.5f,2.5f,1.5f,0.5f,-0.5f,0.5f,1.5f,2.5f,3.5f,4.5f},
  {4.599019514f,3.623105626f,2.662277660f,1.736067977f,0.914213562f,0.5f,0.914213562f,1.736067977f,2.662277660f,3.623105626f,4.599019514f},
  {4.885164807f,3.972135955f,3.105551276f,2.328427125f,1.736067977f,1.5f,1.736067977f,2.328427125f,3.105551276f,3.972135955f,4.885164807f},
  {MK,4.5f,3.742640687f,3.105551276f,2.662277660f,2.5f,2.662277660f,3.105551276f,3.742640687f,4.5f,MK},
  {MK,MK,4.5f,3.972135955f,3.623105626f,3.5f,3.623105626f,3.972135955f,4.5f,MK,MK},
  {MK,MK,MK,4.885164807f,4.599019514f,4.5f,4.599019514f,4.885164807f,MK,MK,MK}
};

__global__ __launch_bounds__(256)
void scatter_render_kernel(const float* __restrict__ x,
                           const float* __restrict__ lens,
                           float* __restrict__ out)
{
    __shared__ float2 s_ec[HY][HX];   // (exp(4*disp), coc)
    __shared__ float2 s_rg[HY][HX];   // (r, g)
    __shared__ float  s_b [HY][HX];   // b

    const int b   = blockIdx.z;
    const int gx0 = blockIdx.x * TX;
    const int gy0 = blockIdx.y * TY;

    const float scale = fabsf(lens[b]);
    const float* __restrict__ xb = x + (size_t)b * 4 * H * W;
    const float* __restrict__ pr = xb;
    const float* __restrict__ pg = xb + H * W;
    const float* __restrict__ pb = xb + 2 * H * W;
    const float* __restrict__ pd = xb + 3 * H * W;

    // ---- cooperative halo-tile fill (with edge clamp) ----
    const int tid = threadIdx.y * TX + threadIdx.x;
    for (int idx = tid; idx < HY * HX; idx += 256) {
        int yy = idx / HX;
        int xx = idx - yy * HX;
        int sy = gy0 + yy - 5; sy = min(max(sy, 0), H - 1);
        int sx = gx0 + xx - 5; sx = min(max(sx, 0), W - 1);
        int o  = sy * W + sx;
        float d  = pd[o];
        float es = __expf(4.0f * d);
        float cc = scale * fabsf(d);
        s_ec[yy][xx] = make_float2(es, cc);
        s_rg[yy][xx] = make_float2(pr[o], pg[o]);
        s_b [yy][xx] = pb[o];
    }
    __syncthreads();

    // ---- main gather: each thread owns 2 vertically adjacent outputs ----
    const int tx = threadIdx.x;
    const int ry = 2 * threadIdx.y;

    const float ed0 = s_ec[ry + 5][tx + 5].x;   // exp(4*disp_dst) for row ry
    const float ed1 = s_ec[ry + 6][tx + 5].x;   // ... for row ry+1

    float nr0 = 0.f, ng0 = 0.f, nb0 = 0.f, nd0 = 0.f;
    float nr1 = 0.f, ng1 = 0.f, nb1 = 0.f, nd1 = 0.f;

    // smem row ry+sr serves out0 as disk row sr (sr=0..10) and out1 as disk
    // row sr-1 (sr=1..11). Only columns inside either disk span are touched.
    #pragma unroll
    for (int sr = 0; sr < 12; ++sr) {
        #pragma unroll
        for (int sc = 0; sc < 11; ++sc) {
            const bool a0 = (sr <= 10) && (sc >= ST[sr])     && (sc < ST[sr]     + WD[sr]);
            const bool a1 = (sr >= 1)  && (sc >= ST[sr - 1]) && (sc < ST[sr - 1] + WD[sr - 1]);
            if (a0 || a1) {
                const float2 ec = s_ec[ry + sr][tx + sc];
                const float2 rg = s_rg[ry + sr][tx + sc];
                const float  bb = s_b [ry + sr][tx + sc];
                if (a0) {
                    const float w0  = __saturatef(ec.y - QD[sr][sc]);
                    const float wo0 = __fdividef(w0 * ec.x, ec.x + ed0);
                    nr0 += wo0 * rg.x;  ng0 += wo0 * rg.y;  nb0 += wo0 * bb;  nd0 += wo0;
                }
                if (a1) {
                    const float w1  = __saturatef(ec.y - QD[sr - 1][sc]);
                    const float wo1 = __fdividef(w1 * ec.x, ec.x + ed1);
                    nr1 += wo1 * rg.x;  ng1 += wo1 * rg.y;  nb1 += wo1 * bb;  nd1 += wo1;
                }
            }
        }
    }

    const int gx = gx0 + tx;
    const int gy = gy0 + ry;
    float* __restrict__ ob = out + (size_t)b * 3 * H * W;
    const float inv0 = __fdividef(1.0f, nd0 + 1e-8f);
    const float inv1 = __fdividef(1.0f, nd1 + 1e-8f);
    const int o0 = gy * W + gx;
    const int o1 = o0 + W;
    ob[o0]             = nr0 * inv0;
    ob[H * W + o0]     = ng0 * inv0;
    ob[2 * H * W + o0] = nb0 * inv0;
    ob[o1]             = nr1 * inv1;
    ob[H * W + o1]     = ng1 * inv1;
    ob[2 * H * W + o1] = nb1 * inv1;
}

extern "C" void kernel_launch(void* const* d_in, const int* in_sizes, int n_in,
                              void* d_out, int out_size)
{
    const float* x    = (const float*)d_in[0];
    const float* lens = (const float*)d_in[1];
    float* out        = (float*)d_out;

    dim3 block(TX, TY / 2, 1);              // 32 x 8 = 256 threads
    dim3 grid(W / TX, H / TY, B);           // 32 x 64 x 4
    scatter_render_kernel<<<grid, block>>>(x, lens, out);
}

// round 11
// speedup vs baseline: 1.5408x; 1.0080x over previous
#include <cuda_runtime.h>

// Problem constants (fixed by setup_inputs)
constexpr int B = 4, H = 1024, W = 1024;
constexpr int TX = 32;          // output tile width
constexpr int TY = 24;          // output tile height (3 rows per thread)
constexpr int HX = TX + 10;     // 42: halo tile width
constexpr int HY = TY + 10;     // 34: halo tile height
constexpr int GY = (H + TY - 1) / TY;   // 43 tiles in y (last partial)

// Disk rows (dy = -5..5): column start and width of the in-mask span, in
// kernel-column coords c = dx+5 (0..10). Row widths 5,7,9,11,11,11,11,11,9,7,5.
__device__ constexpr int ST[11] = {3, 2, 1, 0, 0, 0, 0, 0, 1, 2, 3};
__device__ constexpr int WD[11] = {5, 7, 9, 11, 11, 11, 11, 11, 9, 7, 5};

#define MK 1e30f
// QD[dy+5][dx+5] = dist - 0.5 (entries outside the disk are never evaluated).
__device__ constexpr float QD[11][11] = {
  {MK,MK,MK,4.885164807f,4.599019514f,4.5f,4.599019514f,4.885164807f,MK,MK,MK},
  {MK,MK,4.5f,3.972135955f,3.623105626f,3.5f,3.623105626f,3.972135955f,4.5f,MK,MK},
  {MK,4.5f,3.742640687f,3.105551276f,2.662277660f,2.5f,2.662277660f,3.105551276f,3.742640687f,4.5f,MK},
  {4.885164807f,3.972135955f,3.105551276f,2.328427125f,1.736067977f,1.5f,1.736067977f,2.328427125f,3.105551276f,3.972135955f,4.885164807f},
  {4.599019514f,3.623105626f,2.662277660f,1.736067977f,0.914213562f,0.5f,0.914213562f,1.736067977f,2.662277660f,3.623105626f,4.599019514f},
  {4.5f,3.5f,2.5f,1.5f,0.5f,-0.5f,0.5f,1.5f,2.5f,3.5f,4.5f},
  {4.599019514f,3.623105626f,2.662277660f,1.736067977f,0.914213562f,0.5f,0.914213562f,1.736067977f,2.662277660f,3.623105626f,4.599019514f},
  {4.885164807f,3.972135955f,3.105551276f,2.328427125f,1.736067977f,1.5f,1.736067977f,2.328427125f,3.105551276f,3.972135955f,4.885164807f},
  {MK,4.5f,3.742640687f,3.105551276f,2.662277660f,2.5f,2.662277660f,3.105551276f,3.742640687f,4.5f,MK},
  {MK,MK,4.5f,3.972135955f,3.623105626f,3.5f,3.623105626f,3.972135955f,4.5f,MK,MK},
  {MK,MK,MK,4.885164807f,4.599019514f,4.5f,4.599019514f,4.885164807f,MK,MK,MK}
};

__global__ __launch_bounds__(256)
void scatter_render_kernel(const float* __restrict__ x,
                           const float* __restrict__ lens,
                           float* __restrict__ out)
{
    __shared__ float2 s_ec[HY][HX];   // (exp(4*disp), coc)
    __shared__ float2 s_rg[HY][HX];   // (r, g)
    __shared__ float  s_b [HY][HX];   // b

    const int b   = blockIdx.z;
    const int gx0 = blockIdx.x * TX;
    const int gy0 = blockIdx.y * TY;

    const float scale = fabsf(lens[b]);
    const float* __restrict__ xb = x + (size_t)b * 4 * H * W;
    const float* __restrict__ pr = xb;
    const float* __restrict__ pg = xb + H * W;
    const float* __restrict__ pb = xb + 2 * H * W;
    const float* __restrict__ pd = xb + 3 * H * W;

    // ---- cooperative halo-tile fill (with edge clamp) ----
    const int tid = threadIdx.y * TX + threadIdx.x;
    for (int idx = tid; idx < HY * HX; idx += 256) {
        int yy = idx / HX;
        int xx = idx - yy * HX;
        int sy = gy0 + yy - 5; sy = min(max(sy, 0), H - 1);
        int sx = gx0 + xx - 5; sx = min(max(sx, 0), W - 1);
        int o  = sy * W + sx;
        float d  = pd[o];
        float es = __expf(4.0f * d);
        float cc = scale * fabsf(d);
        s_ec[yy][xx] = make_float2(es, cc);
        s_rg[yy][xx] = make_float2(pr[o], pg[o]);
        s_b [yy][xx] = pb[o];
    }
    __syncthreads();

    // ---- main gather: each thread owns 3 vertically adjacent outputs ----
    const int tx = threadIdx.x;
    const int ry = 3 * threadIdx.y;

    const float ed0 = s_ec[ry + 5][tx + 5].x;   // exp(4*disp_dst), out row ry
    const float ed1 = s_ec[ry + 6][tx + 5].x;
    const float ed2 = s_ec[ry + 7][tx + 5].x;

    float nr0 = 0.f, ng0 = 0.f, nb0 = 0.f, nd0 = 0.f;
    float nr1 = 0.f, ng1 = 0.f, nb1 = 0.f, nd1 = 0.f;
    float nr2 = 0.f, ng2 = 0.f, nb2 = 0.f, nd2 = 0.f;

    // smem row ry+sr serves out_k as disk row r = sr-k (r in [0,10]).
    // Only columns inside some active output's disk span are loaded.
    #pragma unroll
    for (int sr = 0; sr < 13; ++sr) {
        #pragma unroll
        for (int sc = 0; sc < 11; ++sc) {
            const bool a0 = (sr <= 10)              && (sc >= ST[sr])     && (sc < ST[sr]     + WD[sr]);
            const bool a1 = (sr >= 1) && (sr <= 11) && (sc >= ST[sr - 1]) && (sc < ST[sr - 1] + WD[sr - 1]);
            const bool a2 = (sr >= 2)               && (sc >= ST[sr - 2]) && (sc < ST[sr - 2] + WD[sr - 2]);
            if (a0 || a1 || a2) {
                const float2 ec = s_ec[ry + sr][tx + sc];
                const float2 rg = s_rg[ry + sr][tx + sc];
                const float  bb = s_b [ry + sr][tx + sc];
                if (a0) {
                    const float w  = __saturatef(ec.y - QD[sr][sc]);
                    const float wo = __fdividef(w * ec.x, ec.x + ed0);
                    nr0 += wo * rg.x;  ng0 += wo * rg.y;  nb0 += wo * bb;  nd0 += wo;
                }
                if (a1) {
                    const float w  = __saturatef(ec.y - QD[sr - 1][sc]);
                    const float wo = __fdividef(w * ec.x, ec.x + ed1);
                    nr1 += wo * rg.x;  ng1 += wo * rg.y;  nb1 += wo * bb;  nd1 += wo;
                }
                if (a2) {
                    const float w  = __saturatef(ec.y - QD[sr - 2][sc]);
                    const float wo = __fdividef(w * ec.x, ec.x + ed2);
                    nr2 += wo * rg.x;  ng2 += wo * rg.y;  nb2 += wo * bb;  nd2 += wo;
                }
            }
        }
    }

    // ---- epilogue: normalize and store 3 outputs x 3 channels (guarded) ----
    const int gx = gx0 + tx;
    const int gy = gy0 + ry;
    float* __restrict__ ob = out + (size_t)b * 3 * H * W;

    const float i0 = __fdividef(1.0f, nd0 + 1e-8f);
    const float i1 = __fdividef(1.0f, nd1 + 1e-8f);
    const float i2 = __fdividef(1.0f, nd2 + 1e-8f);

    const int o0 = gy * W + gx;
    if (gy < H) {
        ob[o0]             = nr0 * i0;
        ob[H * W + o0]     = ng0 * i0;
        ob[2 * H * W + o0] = nb0 * i0;
    }
    if (gy + 1 < H) {
        ob[o0 + W]             = nr1 * i1;
        ob[H * W + o0 + W]     = ng1 * i1;
        ob[2 * H * W + o0 + W] = nb1 * i1;
    }
    if (gy + 2 < H) {
        ob[o0 + 2 * W]             = nr2 * i2;
        ob[H * W + o0 + 2 * W]     = ng2 * i2;
        ob[2 * H * W + o0 + 2 * W] = nb2 * i2;
    }
}

extern "C" void kernel_launch(void* const* d_in, const int* in_sizes, int n_in,
                              void* d_out, int out_size)
{
    const float* x    = (const float*)d_in[0];
    const float* lens = (const float*)d_in[1];
    float* out        = (float*)d_out;

    dim3 block(TX, 8, 1);                   // 32 x 8 = 256 threads
    dim3 grid(W / TX, GY, B);               // 32 x 43 x 4
    scatter_render_kernel<<<grid, block>>>(x, lens, out);
}